// round 13
// baseline (speedup 1.0000x reference)
#include <cuda_runtime.h>
#include <cstdint>

#define D 128
#define WE 8        // edges per warp per pass
#define HALF 64     // columns per pass

__global__ __launch_bounds__(128, 12)
void tp_fused_kernel(const float* __restrict__ x,
                     const float* __restrict__ y,
                     const float* __restrict__ coeffs,
                     const void* __restrict__ srcp,
                     const void* __restrict__ dstp,
                     float* __restrict__ out,
                     int E, long long n_nodes, int warps_per_pass)
{
    // ---- index dtype detection, once per block (uniform, L2-hit broadcast)
    __shared__ int sh_i64;
    if (threadIdx.x == 0) {
        const long long* s64 = (const long long*)srcp;
        bool ok = true;
#pragma unroll
        for (int i = 0; i < 8; i++) {
            long long v = s64[i];
            if (v < 0 || v >= n_nodes) ok = false;
        }
        sh_i64 = ok ? 1 : 0;
    }
    __syncthreads();
    const bool i64 = (sh_i64 != 0);

    int gid   = blockIdx.x * blockDim.x + threadIdx.x;
    int gwarp = gid >> 5;
    // first half of grid = pass 0 (cols 0..63), second half = pass 1
    int pass  = (gwarp >= warps_per_pass) ? 1 : 0;
    int warp  = gwarp - pass * warps_per_pass;
    int lane  = gid & 31;
    int sub   = lane >> 4;                    // which of 2 concurrent edges
    int l16   = lane & 15;
    int col   = pass * HALF + (l16 << 2);     // 16B chunk in this pass's half-row
    int e0    = warp * WE;
    if (e0 >= E) return;

    // segment = col/32 ; per-pass base segment = pass*2
    float c = __ldg(coeffs + (pass << 1) + (l16 >> 3));

    if (e0 + WE <= E) {
        // ================= fast path: full warp, no predicates =================
        // ---- 1) index loads FIRST (idx->x chain starts at cycle 0)
        unsigned int s[4], d[4];
#pragma unroll
        for (int k = 0; k < 4; k++) {
            int e = e0 + (k << 1) + sub;
            if (i64) {
                s[k] = (unsigned int)((const long long*)srcp)[e];
                d[k] = (unsigned int)((const long long*)dstp)[e];
            } else {
                s[k] = (unsigned int)((const int*)srcp)[e];
                d[k] = (unsigned int)((const int*)dstp)[e];
            }
        }

        // ---- 2) y: streamed once total -> .cs evict-first (overlaps idx trip)
        float4 yv[4];
#pragma unroll
        for (int k = 0; k < 4; k++) {
            int e = e0 + (k << 1) + sub;
            yv[k] = __ldcs(reinterpret_cast<const float4*>(y + (size_t)e * D + col));
        }

        // ---- 3) x gathers: 4 independent L2-hit chains
        float4 xv[4];
#pragma unroll
        for (int k = 0; k < 4; k++) {
            xv[k] = __ldg(reinterpret_cast<const float4*>(x + (size_t)s[k] * D + col));
        }

        // ---- 4) fused multiply + fire-and-forget vector reduction
#pragma unroll
        for (int k = 0; k < 4; k++) {
            float px = xv[k].x * yv[k].x * c;
            float py = xv[k].y * yv[k].y * c;
            float pz = xv[k].z * yv[k].z * c;
            float pw = xv[k].w * yv[k].w * c;
            float* addr = out + (size_t)d[k] * D + col;
            asm volatile("red.global.add.v4.f32 [%0], {%1, %2, %3, %4};"
                         :: "l"(addr), "f"(px), "f"(py), "f"(pz), "f"(pw)
                         : "memory");
        }
    } else {
        // ================= tail warp (never taken when E % WE == 0) ===========
#pragma unroll
        for (int k = 0; k < 4; k++) {
            int e = e0 + (k << 1) + sub;
            if (e < E) {
                unsigned int s, d;
                if (i64) {
                    s = (unsigned int)((const long long*)srcp)[e];
                    d = (unsigned int)((const long long*)dstp)[e];
                } else {
                    s = (unsigned int)((const int*)srcp)[e];
                    d = (unsigned int)((const int*)dstp)[e];
                }
                float4 yv = __ldcs(reinterpret_cast<const float4*>(y + (size_t)e * D + col));
                float4 xv = __ldg (reinterpret_cast<const float4*>(x + (size_t)s * D + col));
                float px = xv.x * yv.x * c;
                float py = xv.y * yv.y * c;
                float pz = xv.z * yv.z * c;
                float pw = xv.w * yv.w * c;
                float* addr = out + (size_t)d * D + col;
                asm volatile("red.global.add.v4.f32 [%0], {%1, %2, %3, %4};"
                             :: "l"(addr), "f"(px), "f"(py), "f"(pz), "f"(pw)
                             : "memory");
            }
        }
    }
}

extern "C" void kernel_launch(void* const* d_in, const int* in_sizes, int n_in,
                              void* d_out, int out_size) {
    const float* x      = (const float*)d_in[0];
    const float* y      = (const float*)d_in[1];
    const float* coeffs = (const float*)d_in[2];
    const void*  src    = d_in[3];
    const void*  dst    = d_in[4];
    float* out = (float*)d_out;

    int E = in_sizes[1] / D;
    long long n_nodes = (long long)(out_size / D);

    // zero the poisoned output via a graph-capturable memset node
    cudaMemsetAsync(d_out, 0, (size_t)out_size * sizeof(float), 0);

    int warps_per_pass = (E + WE - 1) / WE;            // 125k warps per pass
    long long total_threads = (long long)warps_per_pass * 2 * 32;
    int blocks = (int)((total_threads + 127) / 128);

    tp_fused_kernel<<<blocks, 128>>>(x, y, coeffs, src, dst, out,
                                     E, n_nodes, warps_per_pass);
}

// round 14
// speedup vs baseline: 1.3928x; 1.3928x over previous
#include <cuda_runtime.h>
#include <cstdint>

#define D 128
#define WE 8        // edges per warp per pass
#define HALF 64     // columns per pass

__global__ __launch_bounds__(128, 12)
void tp_fused_kernel(const float* __restrict__ x,
                     const float* __restrict__ y,
                     const float* __restrict__ coeffs,
                     const void* __restrict__ srcp,
                     const void* __restrict__ dstp,
                     float* __restrict__ out,
                     int E, long long n_nodes, int warps_per_pass)
{
    // ---- index dtype detection, once per block (uniform, L2-hit broadcast)
    __shared__ int sh_i64;
    if (threadIdx.x == 0) {
        const long long* s64 = (const long long*)srcp;
        bool ok = true;
#pragma unroll
        for (int i = 0; i < 8; i++) {
            long long v = s64[i];
            if (v < 0 || v >= n_nodes) ok = false;
        }
        sh_i64 = ok ? 1 : 0;
    }
    __syncthreads();
    const bool i64 = (sh_i64 != 0);

    int gid   = blockIdx.x * blockDim.x + threadIdx.x;
    int gwarp = gid >> 5;
    // blocks dispatch in order: first half of grid = pass 0, second = pass 1,
    // so the per-pass L2 hot sets stay temporally separated while the
    // pass boundary overlaps (no launch gap, no ramp bubble).
    int pass  = (gwarp >= warps_per_pass) ? 1 : 0;
    int warp  = gwarp - pass * warps_per_pass;
    int lane  = gid & 31;
    int sub   = lane >> 4;                    // which of 2 concurrent edges
    int l16   = lane & 15;
    int col   = pass * HALF + (l16 << 2);     // 16B chunk in this pass's half-row
    int e0    = warp * WE;
    if (e0 >= E) return;

    // ---- 1) index loads up front (4 independent chains per thread)
    unsigned int s[4], d[4];
    bool v[4];
#pragma unroll
    for (int k = 0; k < 4; k++) {
        int e = e0 + (k << 1) + sub;
        v[k] = (e < E);
        if (v[k]) {
            if (i64) {
                s[k] = (unsigned int)((const long long*)srcp)[e];
                d[k] = (unsigned int)((const long long*)dstp)[e];
            } else {
                s[k] = (unsigned int)((const int*)srcp)[e];
                d[k] = (unsigned int)((const int*)dstp)[e];
            }
        } else { s[k] = 0; d[k] = 0; }
    }

    // segment = col/32 ; per-pass base segment = pass*2
    float c = __ldg(coeffs + (pass << 1) + (l16 >> 3));

    // ---- 2) y: streamed once total -> .cs evict-first
    float4 yv[4];
#pragma unroll
    for (int k = 0; k < 4; k++) {
        int e = e0 + (k << 1) + sub;
        yv[k] = __ldcs(reinterpret_cast<const float4*>(
                     y + (size_t)min(e, E - 1) * D + col));
    }

    // ---- 3) x gathers: 4 independent chains; active x half stays L2-resident
    float4 xv[4];
#pragma unroll
    for (int k = 0; k < 4; k++) {
        xv[k] = __ldg(reinterpret_cast<const float4*>(x + (size_t)s[k] * D + col));
    }

    // ---- 4) fused multiply + fire-and-forget vector reduction
#pragma unroll
    for (int k = 0; k < 4; k++) {
        if (v[k]) {
            float px = xv[k].x * yv[k].x * c;
            float py = xv[k].y * yv[k].y * c;
            float pz = xv[k].z * yv[k].z * c;
            float pw = xv[k].w * yv[k].w * c;
            float* addr = out + (size_t)d[k] * D + col;
            asm volatile("red.global.add.v4.f32 [%0], {%1, %2, %3, %4};"
                         :: "l"(addr), "f"(px), "f"(py), "f"(pz), "f"(pw)
                         : "memory");
        }
    }
}

extern "C" void kernel_launch(void* const* d_in, const int* in_sizes, int n_in,
                              void* d_out, int out_size) {
    const float* x      = (const float*)d_in[0];
    const float* y      = (const float*)d_in[1];
    const float* coeffs = (const float*)d_in[2];
    const void*  src    = d_in[3];
    const void*  dst    = d_in[4];
    float* out = (float*)d_out;

    int E = in_sizes[1] / D;
    long long n_nodes = (long long)(out_size / D);

    // zero the poisoned output via a graph-capturable memset node
    cudaMemsetAsync(d_out, 0, (size_t)out_size * sizeof(float), 0);

    int warps_per_pass = (E + WE - 1) / WE;            // 125k warps per pass
    long long total_threads = (long long)warps_per_pass * 2 * 32;
    int blocks = (int)((total_threads + 127) / 128);

    tp_fused_kernel<<<blocks, 128>>>(x, y, coeffs, src, dst, out,
                                     E, n_nodes, warps_per_pass);
}